// round 1
// baseline (speedup 1.0000x reference)
#include <cuda_runtime.h>
#include <math.h>

#define EMB 64
#define HID 128
#define NN  50000
#define NE  800000
#define NQ  64

// ---------------- scratch (static device globals; no allocation) ----------------
__device__ float g_qr[NQ * EMB];        // q_repr = qe@Wq + bq
__device__ float g_Aq[NQ * EMB];        // q_repr @ W1a
__device__ float g_M [EMB * EMB];       // Wr @ W1c   (folded relation projection)
__device__ float g_Mb[EMB * EMB];       // We @ W1b
__device__ float g_Md[EMB * EMB];       // We @ W1d
__device__ float g_biasAB[EMB];         // b1 + be@W1b + br@W1c
__device__ float g_biasC [EMB];         // be@W1d
__device__ float g_ABn[NN * EMB];       // per-node: ne@Mb + biasAB + Aq[batch[n]]
__device__ float g_Cn [NN * EMB];       // per-node: ne@Md + biasC

// ---------------- prep 0: q_repr ----------------
__global__ void prep0_kernel(const float* __restrict__ qe,
                             const float* __restrict__ Wq,
                             const float* __restrict__ bq) {
    int idx = blockIdx.x * 256 + threadIdx.x;   // 16 blocks x 256 = 4096
    int q = idx >> 6, j = idx & 63;
    float s = bq[j];
    #pragma unroll 8
    for (int i = 0; i < EMB; i++) s += qe[q * EMB + i] * Wq[i * EMB + j];
    g_qr[idx] = s;
}

// ---------------- prep 1: folded matrices + biases ----------------
__global__ void prep1_kernel(const float* __restrict__ We,
                             const float* __restrict__ be,
                             const float* __restrict__ Wr,
                             const float* __restrict__ br,
                             const float* __restrict__ W1,
                             const float* __restrict__ b1) {
    int b = blockIdx.x;
    if (b < 64) {
        int m   = b >> 4;                         // which matrix (0..3)
        int idx = (b & 15) * 256 + threadIdx.x;   // 0..4095
        int k = idx >> 6, j = idx & 63;
        float s = 0.f;
        if (m == 0) {
            #pragma unroll 8
            for (int i = 0; i < EMB; i++) s += g_qr[k * EMB + i] * W1[i * EMB + j];
            g_Aq[idx] = s;
        } else if (m == 1) {
            #pragma unroll 8
            for (int i = 0; i < EMB; i++) s += Wr[k * EMB + i] * W1[(128 + i) * EMB + j];
            g_M[idx] = s;
        } else if (m == 2) {
            #pragma unroll 8
            for (int i = 0; i < EMB; i++) s += We[k * EMB + i] * W1[(64 + i) * EMB + j];
            g_Mb[idx] = s;
        } else {
            #pragma unroll 8
            for (int i = 0; i < EMB; i++) s += We[k * EMB + i] * W1[(192 + i) * EMB + j];
            g_Md[idx] = s;
        }
    } else {
        if (threadIdx.x < EMB) {
            int j = threadIdx.x;
            float sAB = b1[j], sC = 0.f;
            #pragma unroll 8
            for (int i = 0; i < EMB; i++) {
                sAB += be[i] * W1[(64 + i) * EMB + j] + br[i] * W1[(128 + i) * EMB + j];
                sC  += be[i] * W1[(192 + i) * EMB + j];
            }
            g_biasAB[j] = sAB;
            g_biasC[j]  = sC;
        }
    }
}

// ---------------- node table kernel: 32 nodes per block ----------------
__global__ __launch_bounds__(256) void node_kernel(const float* __restrict__ nodeEmb,
                                                   const int*   __restrict__ nodeBatch) {
    __shared__ float sMb[EMB * EMB];
    __shared__ float sMd[EMB * EMB];
    __shared__ float sNe[32 * 65];
    int t = threadIdx.x;

    for (int i = t; i < 1024; i += 256) {
        ((float4*)sMb)[i] = ((const float4*)g_Mb)[i];
        ((float4*)sMd)[i] = ((const float4*)g_Md)[i];
    }
    int n0 = blockIdx.x * 32;
    for (int i = t; i < 512; i += 256) {            // 32 rows x 16 float4
        int r = i >> 4, c4 = (i & 15) << 2;
        int n = n0 + r;
        float4 v = (n < NN) ? ((const float4*)nodeEmb)[n * 16 + (i & 15)]
                            : make_float4(0.f, 0.f, 0.f, 0.f);
        float* d = &sNe[r * 65 + c4];
        d[0] = v.x; d[1] = v.y; d[2] = v.z; d[3] = v.w;
    }
    __syncthreads();

    int r = t >> 3, j0 = (t & 7) << 3;
    int n = n0 + r;
    float accA[8] = {0,0,0,0,0,0,0,0};
    float accC[8] = {0,0,0,0,0,0,0,0};
    #pragma unroll 8
    for (int k = 0; k < EMB; k++) {
        float a = sNe[r * 65 + k];
        const float4* mb = (const float4*)&sMb[k * EMB + j0];
        const float4* md = (const float4*)&sMd[k * EMB + j0];
        float4 w0 = mb[0], w1 = mb[1], v0 = md[0], v1 = md[1];
        accA[0] += a * w0.x; accA[1] += a * w0.y; accA[2] += a * w0.z; accA[3] += a * w0.w;
        accA[4] += a * w1.x; accA[5] += a * w1.y; accA[6] += a * w1.z; accA[7] += a * w1.w;
        accC[0] += a * v0.x; accC[1] += a * v0.y; accC[2] += a * v0.z; accC[3] += a * v0.w;
        accC[4] += a * v1.x; accC[5] += a * v1.y; accC[6] += a * v1.z; accC[7] += a * v1.w;
    }
    if (n < NN) {
        int qid = nodeBatch[n];
        const float* aq = g_Aq + qid * EMB + j0;
        float* oA = g_ABn + n * EMB + j0;
        float* oC = g_Cn  + n * EMB + j0;
        #pragma unroll
        for (int j = 0; j < 8; j++) {
            oA[j] = accA[j] + g_biasAB[j0 + j] + aq[j];
            oC[j] = accC[j] + g_biasC[j0 + j];
        }
    }
}

// ---------------- edge kernel: 64 edges per block, fused pipeline ----------------
// smem layout (floats): sM[4096] | sW2[8192] | sEH[64*65] | sWh[128] | sb2[128] | sHT[128 ints]
#define SME_FLOATS (4096 + 8192 + 64 * 65 + 128 + 128)
#define SME_BYTES  (SME_FLOATS * 4 + 128 * 4)

__global__ __launch_bounds__(256) void edge_kernel(const float* __restrict__ edgeEmb,
                                                   const int*   __restrict__ edgeIndex,
                                                   const float* __restrict__ W2,
                                                   const float* __restrict__ b2,
                                                   const float* __restrict__ Wh,
                                                   const float* __restrict__ bh,
                                                   float* __restrict__ out) {
    extern __shared__ float sm[];
    float* sM  = sm;                     // 64x64
    float* sW2 = sm + 4096;              // 64x128
    float* sEH = sm + 4096 + 8192;       // 64x65 (edge_emb tile, then reused for h)
    float* sWh = sEH + 64 * 65;          // 128
    float* sb2 = sWh + 128;              // 128
    int*   sHT = (int*)(sb2 + 128);      // head[64], tail[64]

    int t = threadIdx.x;
    for (int i = t; i < 1024; i += 256) ((float4*)sM )[i] = ((const float4*)g_M)[i];
    for (int i = t; i < 2048; i += 256) ((float4*)sW2)[i] = ((const float4*)W2)[i];
    if (t < 128) { sWh[t] = Wh[t]; sb2[t] = b2[t]; }

    int e0 = blockIdx.x * 64;
    if (t < 64) {
        sHT[t]      = edgeIndex[e0 + t];        // head
        sHT[64 + t] = edgeIndex[NE + e0 + t];   // tail
    }
    for (int i = t; i < 1024; i += 256) {       // 64 rows x 16 float4
        int r = i >> 4, c4 = (i & 15) << 2;
        float4 v = ((const float4*)edgeEmb)[(size_t)(e0 + r) * 16 + (i & 15)];
        float* d = &sEH[r * 65 + c4];
        d[0] = v.x; d[1] = v.y; d[2] = v.z; d[3] = v.w;
    }
    __syncthreads();

    // ---- stage 1: h[r][j0..j0+15] = relu( ee[r]@M + ABn[head] + Cn[tail] ) ----
    int r  = t >> 2;
    int j0 = (t & 3) << 4;
    int head = sHT[r], tail = sHT[64 + r];

    float acc[16];
    {
        const float4* pa = (const float4*)(g_ABn + (size_t)head * EMB + j0);
        const float4* pc = (const float4*)(g_Cn  + (size_t)tail * EMB + j0);
        #pragma unroll
        for (int m = 0; m < 4; m++) {
            float4 A = pa[m], C = pc[m];
            acc[4*m+0] = A.x + C.x; acc[4*m+1] = A.y + C.y;
            acc[4*m+2] = A.z + C.z; acc[4*m+3] = A.w + C.w;
        }
    }
    #pragma unroll 8
    for (int k = 0; k < EMB; k++) {
        float a = sEH[r * 65 + k];
        const float4* m4 = (const float4*)&sM[k * EMB + j0];
        #pragma unroll
        for (int m = 0; m < 4; m++) {
            float4 w = m4[m];
            acc[4*m+0] += a * w.x; acc[4*m+1] += a * w.y;
            acc[4*m+2] += a * w.z; acc[4*m+3] += a * w.w;
        }
    }
    #pragma unroll
    for (int j = 0; j < 16; j++) acc[j] = fmaxf(acc[j], 0.f);

    __syncthreads();                      // everyone done reading ee tile
    {
        float* d = &sEH[r * 65 + j0];
        #pragma unroll
        for (int j = 0; j < 16; j++) d[j] = acc[j];
    }
    __syncthreads();                      // h tile ready

    // ---- stage 2: z = relu(h@W2 + b2); logit = z.Wh + bh; out = sigmoid ----
    int j0b = (t & 3) << 5;               // 32 HID columns per lane
    float z[32];
    #pragma unroll
    for (int j = 0; j < 32; j++) z[j] = sb2[j0b + j];
    #pragma unroll 4
    for (int k = 0; k < EMB; k++) {
        float hv = sEH[r * 65 + k];
        const float4* w4 = (const float4*)&sW2[k * HID + j0b];
        #pragma unroll
        for (int m = 0; m < 8; m++) {
            float4 w = w4[m];
            z[4*m+0] += hv * w.x; z[4*m+1] += hv * w.y;
            z[4*m+2] += hv * w.z; z[4*m+3] += hv * w.w;
        }
    }
    float part = 0.f;
    #pragma unroll
    for (int j = 0; j < 32; j++) part += fmaxf(z[j], 0.f) * sWh[j0b + j];
    part += __shfl_xor_sync(0xffffffffu, part, 1);
    part += __shfl_xor_sync(0xffffffffu, part, 2);
    if ((t & 3) == 0) {
        float logit = part + bh[0];
        out[e0 + r] = 1.f / (1.f + expf(-logit));
    }
}

// ---------------- launch ----------------
extern "C" void kernel_launch(void* const* d_in, const int* in_sizes, int n_in,
                              void* d_out, int out_size) {
    const float* question_emb = (const float*)d_in[0];
    const float* node_emb     = (const float*)d_in[1];
    const float* edge_emb     = (const float*)d_in[2];
    const int*   edge_index   = (const int*)  d_in[3];
    const int*   node_batch   = (const int*)  d_in[4];
    const float* Wq = (const float*)d_in[5];
    const float* bq = (const float*)d_in[6];
    const float* We = (const float*)d_in[7];
    const float* be = (const float*)d_in[8];
    const float* Wr = (const float*)d_in[9];
    const float* br = (const float*)d_in[10];
    const float* W1 = (const float*)d_in[11];
    const float* b1 = (const float*)d_in[12];
    const float* W2 = (const float*)d_in[13];
    const float* b2 = (const float*)d_in[14];
    const float* Wh = (const float*)d_in[15];
    const float* bh = (const float*)d_in[16];
    float* out = (float*)d_out;

    prep0_kernel<<<16, 256>>>(question_emb, Wq, bq);
    prep1_kernel<<<65, 256>>>(We, be, Wr, br, W1, b1);
    node_kernel<<<(NN + 31) / 32, 256>>>(node_emb, node_batch);

    cudaFuncSetAttribute(edge_kernel, cudaFuncAttributeMaxDynamicSharedMemorySize, SME_BYTES);
    edge_kernel<<<NE / 64, 256, SME_BYTES>>>(edge_emb, edge_index, W2, b2, Wh, bh, out);
}

// round 2
// speedup vs baseline: 5.4992x; 5.4992x over previous
#include <cuda_runtime.h>
#include <math.h>
#include <stdint.h>

#define EMB 64
#define HID 128
#define NN  50000
#define NE  800000
#define NQ  64

// ---------------- scratch (static device globals; no allocation) ----------------
__device__ float g_qr[NQ * EMB];        // q_repr = qe@Wq + bq
__device__ float g_Aq[NQ * EMB];        // q_repr @ W1a
__device__ float g_M [EMB * EMB];       // Wr @ W1c   (folded relation projection)
__device__ float g_Mb[EMB * EMB];       // We @ W1b
__device__ float g_Md[EMB * EMB];       // We @ W1d
__device__ float g_biasAB[EMB];         // b1 + be@W1b + br@W1c
__device__ float g_biasC [EMB];         // be@W1d
__device__ float g_ABn[NN * EMB];       // per-node: ne@Mb + biasAB + Aq[batch[n]]
__device__ float g_Cn [NN * EMB];       // per-node: ne@Md + biasC

// ---------------- tf32 helpers ----------------
__device__ __forceinline__ uint32_t f2tf32(float x) {
    uint32_t r;
    asm("cvt.rna.tf32.f32 %0, %1;" : "=r"(r) : "f"(x));
    return r;
}
__device__ __forceinline__ float tf32r(float x) {   // round-to-tf32, keep as float bits
    return __uint_as_float(f2tf32(x));
}
__device__ __forceinline__ void mma_tf32(float& c0, float& c1, float& c2, float& c3,
                                         uint32_t a0, uint32_t a1, uint32_t a2, uint32_t a3,
                                         uint32_t b0, uint32_t b1) {
    asm volatile("mma.sync.aligned.m16n8k8.row.col.f32.tf32.tf32.f32 "
                 "{%0,%1,%2,%3}, {%4,%5,%6,%7}, {%8,%9}, {%0,%1,%2,%3};\n"
                 : "+f"(c0), "+f"(c1), "+f"(c2), "+f"(c3)
                 : "r"(a0), "r"(a1), "r"(a2), "r"(a3), "r"(b0), "r"(b1));
}

// ---------------- prep 0: q_repr ----------------
__global__ void prep0_kernel(const float* __restrict__ qe,
                             const float* __restrict__ Wq,
                             const float* __restrict__ bq) {
    int idx = blockIdx.x * 256 + threadIdx.x;   // 16 blocks x 256 = 4096
    int q = idx >> 6, j = idx & 63;
    float s = bq[j];
    #pragma unroll 8
    for (int i = 0; i < EMB; i++) s += qe[q * EMB + i] * Wq[i * EMB + j];
    g_qr[idx] = s;
}

// ---------------- prep 1: folded matrices + biases ----------------
__global__ void prep1_kernel(const float* __restrict__ We,
                             const float* __restrict__ be,
                             const float* __restrict__ Wr,
                             const float* __restrict__ br,
                             const float* __restrict__ W1,
                             const float* __restrict__ b1) {
    int b = blockIdx.x;
    if (b < 64) {
        int m   = b >> 4;                         // which matrix (0..3)
        int idx = (b & 15) * 256 + threadIdx.x;   // 0..4095
        int k = idx >> 6, j = idx & 63;
        float s = 0.f;
        if (m == 0) {
            #pragma unroll 8
            for (int i = 0; i < EMB; i++) s += g_qr[k * EMB + i] * W1[i * EMB + j];
            g_Aq[idx] = s;
        } else if (m == 1) {
            #pragma unroll 8
            for (int i = 0; i < EMB; i++) s += Wr[k * EMB + i] * W1[(128 + i) * EMB + j];
            g_M[idx] = s;
        } else if (m == 2) {
            #pragma unroll 8
            for (int i = 0; i < EMB; i++) s += We[k * EMB + i] * W1[(64 + i) * EMB + j];
            g_Mb[idx] = s;
        } else {
            #pragma unroll 8
            for (int i = 0; i < EMB; i++) s += We[k * EMB + i] * W1[(192 + i) * EMB + j];
            g_Md[idx] = s;
        }
    } else {
        if (threadIdx.x < EMB) {
            int j = threadIdx.x;
            float sAB = b1[j], sC = 0.f;
            #pragma unroll 8
            for (int i = 0; i < EMB; i++) {
                sAB += be[i] * W1[(64 + i) * EMB + j] + br[i] * W1[(128 + i) * EMB + j];
                sC  += be[i] * W1[(192 + i) * EMB + j];
            }
            g_biasAB[j] = sAB;
            g_biasC[j]  = sC;
        }
    }
}

// ---------------- node table kernel: 32 nodes per block ----------------
__global__ __launch_bounds__(256) void node_kernel(const float* __restrict__ nodeEmb,
                                                   const int*   __restrict__ nodeBatch) {
    __shared__ float sMb[EMB * EMB];
    __shared__ float sMd[EMB * EMB];
    __shared__ float sNe[32 * 65];
    int t = threadIdx.x;

    for (int i = t; i < 1024; i += 256) {
        ((float4*)sMb)[i] = ((const float4*)g_Mb)[i];
        ((float4*)sMd)[i] = ((const float4*)g_Md)[i];
    }
    int n0 = blockIdx.x * 32;
    for (int i = t; i < 512; i += 256) {            // 32 rows x 16 float4
        int r = i >> 4, c4 = (i & 15) << 2;
        int n = n0 + r;
        float4 v = (n < NN) ? ((const float4*)nodeEmb)[n * 16 + (i & 15)]
                            : make_float4(0.f, 0.f, 0.f, 0.f);
        float* d = &sNe[r * 65 + c4];
        d[0] = v.x; d[1] = v.y; d[2] = v.z; d[3] = v.w;
    }
    __syncthreads();

    int r = t >> 3, j0 = (t & 7) << 3;
    int n = n0 + r;
    float accA[8] = {0,0,0,0,0,0,0,0};
    float accC[8] = {0,0,0,0,0,0,0,0};
    #pragma unroll 8
    for (int k = 0; k < EMB; k++) {
        float a = sNe[r * 65 + k];
        const float4* mb = (const float4*)&sMb[k * EMB + j0];
        const float4* md = (const float4*)&sMd[k * EMB + j0];
        float4 w0 = mb[0], w1 = mb[1], v0 = md[0], v1 = md[1];
        accA[0] += a * w0.x; accA[1] += a * w0.y; accA[2] += a * w0.z; accA[3] += a * w0.w;
        accA[4] += a * w1.x; accA[5] += a * w1.y; accA[6] += a * w1.z; accA[7] += a * w1.w;
        accC[0] += a * v0.x; accC[1] += a * v0.y; accC[2] += a * v0.z; accC[3] += a * v0.w;
        accC[4] += a * v1.x; accC[5] += a * v1.y; accC[6] += a * v1.z; accC[7] += a * v1.w;
    }
    if (n < NN) {
        int qid = nodeBatch[n];
        const float* aq = g_Aq + qid * EMB + j0;
        float* oA = g_ABn + n * EMB + j0;
        float* oC = g_Cn  + n * EMB + j0;
        #pragma unroll
        for (int j = 0; j < 8; j++) {
            oA[j] = accA[j] + g_biasAB[j0 + j] + aq[j];
            oC[j] = accC[j] + g_biasC[j0 + j];
        }
    }
}

// ---------------- edge kernel: 128 edges/block, tf32 mma pipeline ----------------
// smem floats:
//   sEE  [128 x 68]  edge emb tile (pre-rounded tf32)        offset 0
//   sG   [128 x 68]  gathered ABn+Cn (fp32), reused as H     offset 8704
//   sM   [ 64 x 72]  folded relation matrix (tf32)           offset 17408
//   sW2  [ 64 x 136] W2 (tf32)                               offset 22016
//   sWh  [128], sb2 [128]                                    offset 30720, 30848
//   sHT  [256] ints (head[128], tail[128])                   offset 30976 floats
#define EE_S 68
#define M_S  72
#define W2_S 136
#define OFF_EE 0
#define OFF_G  8704
#define OFF_M  17408
#define OFF_W2 22016
#define OFF_WH 30720
#define OFF_B2 30848
#define OFF_HT 30976
#define SME_BYTES ((30976 + 256) * 4)

__global__ __launch_bounds__(256) void edge_kernel(const float* __restrict__ edgeEmb,
                                                   const int*   __restrict__ edgeIndex,
                                                   const float* __restrict__ W2,
                                                   const float* __restrict__ b2,
                                                   const float* __restrict__ Wh,
                                                   const float* __restrict__ bh,
                                                   float* __restrict__ out) {
    extern __shared__ float sm[];
    float* sEE = sm + OFF_EE;
    float* sG  = sm + OFF_G;
    float* sM  = sm + OFF_M;
    float* sW2 = sm + OFF_W2;
    float* sWh = sm + OFF_WH;
    float* sb2 = sm + OFF_B2;
    int*   sHT = (int*)(sm + OFF_HT);

    int t = threadIdx.x;
    int e0 = blockIdx.x * 128;

    // --- fills (all independent of sHT except sG) ---
    if (t < 128) {
        sHT[t]       = edgeIndex[e0 + t];        // head
        sHT[128 + t] = edgeIndex[NE + e0 + t];   // tail
        sWh[t] = Wh[t];
        sb2[t] = b2[t];
    }
    // edge emb tile: 128 rows x 16 float4, pre-rounded to tf32
    for (int i = t; i < 2048; i += 256) {
        int r = i >> 4, c4 = (i & 15) << 2;
        float4 v = ((const float4*)edgeEmb)[(size_t)(e0 + r) * 16 + (i & 15)];
        float* d = &sEE[r * EE_S + c4];
        d[0] = tf32r(v.x); d[1] = tf32r(v.y); d[2] = tf32r(v.z); d[3] = tf32r(v.w);
    }
    // M (64x64) -> stride 72, tf32
    for (int i = t; i < 1024; i += 256) {
        int r = i >> 4, c4 = (i & 15) << 2;
        float4 v = ((const float4*)g_M)[i];
        float* d = &sM[r * M_S + c4];
        d[0] = tf32r(v.x); d[1] = tf32r(v.y); d[2] = tf32r(v.z); d[3] = tf32r(v.w);
    }
    // W2 (64x128) -> stride 136, tf32
    for (int i = t; i < 2048; i += 256) {
        int r = i >> 5, c4 = (i & 31) << 2;
        float4 v = ((const float4*)W2)[i];
        float* d = &sW2[r * W2_S + c4];
        d[0] = tf32r(v.x); d[1] = tf32r(v.y); d[2] = tf32r(v.z); d[3] = tf32r(v.w);
    }
    __syncthreads();

    // gathered tables: G[r][:] = ABn[head[r]] + Cn[tail[r]]   (exact fp32)
    for (int i = t; i < 2048; i += 256) {
        int r = i >> 4, c4 = (i & 15) << 2;
        int head = sHT[r], tail = sHT[128 + r];
        float4 A = ((const float4*)(g_ABn + (size_t)head * EMB))[i & 15];
        float4 C = ((const float4*)(g_Cn  + (size_t)tail * EMB))[i & 15];
        float* d = &sG[r * EE_S + c4];
        d[0] = A.x + C.x; d[1] = A.y + C.y; d[2] = A.z + C.z; d[3] = A.w + C.w;
    }
    __syncthreads();

    // --- per-warp fragment coordinates (warp w owns rows 16w..16w+15) ---
    int w    = t >> 5;
    int lane = t & 31;
    int g    = lane >> 2;       // 0..7
    int tig  = lane & 3;        // 0..3
    int rA = w * 16 + g;        // fragment row (and rA+8)

    // ================= stage 1: H = relu(EE @ M + G) =================
    float acc[32];
    #pragma unroll
    for (int nt = 0; nt < 8; nt++) {
        int n0 = nt * 8 + 2 * tig;
        acc[nt*4+0] = sG[rA * EE_S + n0];
        acc[nt*4+1] = sG[rA * EE_S + n0 + 1];
        acc[nt*4+2] = sG[(rA + 8) * EE_S + n0];
        acc[nt*4+3] = sG[(rA + 8) * EE_S + n0 + 1];
    }
    __syncwarp();   // all lanes' G reads complete before any lane overwrites sG with H

    #pragma unroll
    for (int kt = 0; kt < 8; kt++) {
        int k0 = kt * 8;
        uint32_t a0 = __float_as_uint(sEE[rA * EE_S + k0 + tig]);
        uint32_t a1 = __float_as_uint(sEE[(rA + 8) * EE_S + k0 + tig]);
        uint32_t a2 = __float_as_uint(sEE[rA * EE_S + k0 + tig + 4]);
        uint32_t a3 = __float_as_uint(sEE[(rA + 8) * EE_S + k0 + tig + 4]);
        #pragma unroll
        for (int nt = 0; nt < 8; nt++) {
            uint32_t b0 = __float_as_uint(sM[(k0 + tig) * M_S + nt * 8 + g]);
            uint32_t b1 = __float_as_uint(sM[(k0 + tig + 4) * M_S + nt * 8 + g]);
            mma_tf32(acc[nt*4], acc[nt*4+1], acc[nt*4+2], acc[nt*4+3],
                     a0, a1, a2, a3, b0, b1);
        }
    }
    // relu + store H back into sG (each warp writes only its own 16 rows)
    #pragma unroll
    for (int nt = 0; nt < 8; nt++) {
        int n0 = nt * 8 + 2 * tig;
        sG[rA * EE_S + n0]           = fmaxf(acc[nt*4+0], 0.f);
        sG[rA * EE_S + n0 + 1]       = fmaxf(acc[nt*4+1], 0.f);
        sG[(rA + 8) * EE_S + n0]     = fmaxf(acc[nt*4+2], 0.f);
        sG[(rA + 8) * EE_S + n0 + 1] = fmaxf(acc[nt*4+3], 0.f);
    }
    __syncwarp();

    // ================= stage 2: z = relu(H @ W2 + b2); logit = z.Wh =================
    float acc2[64];
    #pragma unroll
    for (int nt = 0; nt < 16; nt++) {
        float bz0 = sb2[nt * 8 + 2 * tig];
        float bz1 = sb2[nt * 8 + 2 * tig + 1];
        acc2[nt*4+0] = bz0; acc2[nt*4+1] = bz1;
        acc2[nt*4+2] = bz0; acc2[nt*4+3] = bz1;
    }
    #pragma unroll
    for (int kt = 0; kt < 8; kt++) {
        int k0 = kt * 8;
        uint32_t a0 = f2tf32(sG[rA * EE_S + k0 + tig]);
        uint32_t a1 = f2tf32(sG[(rA + 8) * EE_S + k0 + tig]);
        uint32_t a2 = f2tf32(sG[rA * EE_S + k0 + tig + 4]);
        uint32_t a3 = f2tf32(sG[(rA + 8) * EE_S + k0 + tig + 4]);
        #pragma unroll
        for (int nt = 0; nt < 16; nt++) {
            uint32_t b0 = __float_as_uint(sW2[(k0 + tig) * W2_S + nt * 8 + g]);
            uint32_t b1 = __float_as_uint(sW2[(k0 + tig + 4) * W2_S + nt * 8 + g]);
            mma_tf32(acc2[nt*4], acc2[nt*4+1], acc2[nt*4+2], acc2[nt*4+3],
                     a0, a1, a2, a3, b0, b1);
        }
    }
    // epilogue: relu, dot with Wh, quad-reduce, sigmoid
    float p0 = 0.f, p1 = 0.f;
    #pragma unroll
    for (int nt = 0; nt < 16; nt++) {
        float w0 = sWh[nt * 8 + 2 * tig];
        float w1 = sWh[nt * 8 + 2 * tig + 1];
        p0 += fmaxf(acc2[nt*4+0], 0.f) * w0 + fmaxf(acc2[nt*4+1], 0.f) * w1;
        p1 += fmaxf(acc2[nt*4+2], 0.f) * w0 + fmaxf(acc2[nt*4+3], 0.f) * w1;
    }
    p0 += __shfl_xor_sync(0xffffffffu, p0, 1);
    p0 += __shfl_xor_sync(0xffffffffu, p0, 2);
    p1 += __shfl_xor_sync(0xffffffffu, p1, 1);
    p1 += __shfl_xor_sync(0xffffffffu, p1, 2);
    if (tig == 0) {
        float bhv = bh[0];
        out[e0 + rA]     = 1.f / (1.f + expf(-(p0 + bhv)));
        out[e0 + rA + 8] = 1.f / (1.f + expf(-(p1 + bhv)));
    }
}

// ---------------- launch ----------------
extern "C" void kernel_launch(void* const* d_in, const int* in_sizes, int n_in,
                              void* d_out, int out_size) {
    const float* question_emb = (const float*)d_in[0];
    const float* node_emb     = (const float*)d_in[1];
    const float* edge_emb     = (const float*)d_in[2];
    const int*   edge_index   = (const int*)  d_in[3];
    const int*   node_batch   = (const int*)  d_in[4];
    const float* Wq = (const float*)d_in[5];
    const float* bq = (const float*)d_in[6];
    const float* We = (const float*)d_in[7];
    const float* be = (const float*)d_in[8];
    const float* Wr = (const float*)d_in[9];
    const float* br = (const float*)d_in[10];
    const float* W1 = (const float*)d_in[11];
    const float* b1 = (const float*)d_in[12];
    const float* W2 = (const float*)d_in[13];
    const float* b2 = (const float*)d_in[14];
    const float* Wh = (const float*)d_in[15];
    const float* bh = (const float*)d_in[16];
    float* out = (float*)d_out;

    prep0_kernel<<<16, 256>>>(question_emb, Wq, bq);
    prep1_kernel<<<65, 256>>>(We, be, Wr, br, W1, b1);
    node_kernel<<<(NN + 31) / 32, 256>>>(node_emb, node_batch);

    cudaFuncSetAttribute(edge_kernel, cudaFuncAttributeMaxDynamicSharedMemorySize, SME_BYTES);
    edge_kernel<<<NE / 128, 256, SME_BYTES>>>(edge_emb, edge_index, W2, b2, Wh, bh, out);
}

// round 3
// speedup vs baseline: 14.9440x; 2.7175x over previous
#include <cuda_runtime.h>
#include <math.h>
#include <stdint.h>

#define EMB 64
#define HID 128
#define NN  50000
#define NE  800000
#define NQ  64
#define NTILES (NE / 128)

// ---------------- scratch (static device globals; no allocation) ----------------
__device__ float g_qr[NQ * EMB];        // q_repr = qe@Wq + bq
__device__ float g_Aq[NQ * EMB];        // q_repr @ W1a
__device__ float g_M [EMB * EMB];       // Wr @ W1c   (folded relation projection)
__device__ float g_Mb[EMB * EMB];       // We @ W1b
__device__ float g_Md[EMB * EMB];       // We @ W1d
__device__ float g_biasAB[EMB];         // b1 + be@W1b + br@W1c
__device__ float g_biasC [EMB];         // be@W1d
__device__ float g_ABn[NN * EMB];       // per-node: ne@Mb + biasAB + Aq[batch[n]]
__device__ float g_Cn [NN * EMB];       // per-node: ne@Md + biasC

// ---------------- tf32 helpers ----------------
__device__ __forceinline__ uint32_t f2tf32(float x) {
    uint32_t r;
    asm("cvt.rna.tf32.f32 %0, %1;" : "=r"(r) : "f"(x));
    return r;
}
__device__ __forceinline__ float tf32r(float x) {
    return __uint_as_float(f2tf32(x));
}
__device__ __forceinline__ void mma_tf32(float& c0, float& c1, float& c2, float& c3,
                                         uint32_t a0, uint32_t a1, uint32_t a2, uint32_t a3,
                                         uint32_t b0, uint32_t b1) {
    asm volatile("mma.sync.aligned.m16n8k8.row.col.f32.tf32.tf32.f32 "
                 "{%0,%1,%2,%3}, {%4,%5,%6,%7}, {%8,%9}, {%0,%1,%2,%3};\n"
                 : "+f"(c0), "+f"(c1), "+f"(c2), "+f"(c3)
                 : "r"(a0), "r"(a1), "r"(a2), "r"(a3), "r"(b0), "r"(b1));
}

// ---------------- prep 0: q_repr ----------------
__global__ void prep0_kernel(const float* __restrict__ qe,
                             const float* __restrict__ Wq,
                             const float* __restrict__ bq) {
    int idx = blockIdx.x * 256 + threadIdx.x;
    int q = idx >> 6, j = idx & 63;
    float s = bq[j];
    #pragma unroll 8
    for (int i = 0; i < EMB; i++) s += qe[q * EMB + i] * Wq[i * EMB + j];
    g_qr[idx] = s;
}

// ---------------- prep 1: folded matrices + biases ----------------
__global__ void prep1_kernel(const float* __restrict__ We,
                             const float* __restrict__ be,
                             const float* __restrict__ Wr,
                             const float* __restrict__ br,
                             const float* __restrict__ W1,
                             const float* __restrict__ b1) {
    int b = blockIdx.x;
    if (b < 64) {
        int m   = b >> 4;
        int idx = (b & 15) * 256 + threadIdx.x;
        int k = idx >> 6, j = idx & 63;
        float s = 0.f;
        if (m == 0) {
            #pragma unroll 8
            for (int i = 0; i < EMB; i++) s += g_qr[k * EMB + i] * W1[i * EMB + j];
            g_Aq[idx] = s;
        } else if (m == 1) {
            #pragma unroll 8
            for (int i = 0; i < EMB; i++) s += Wr[k * EMB + i] * W1[(128 + i) * EMB + j];
            g_M[idx] = s;
        } else if (m == 2) {
            #pragma unroll 8
            for (int i = 0; i < EMB; i++) s += We[k * EMB + i] * W1[(64 + i) * EMB + j];
            g_Mb[idx] = s;
        } else {
            #pragma unroll 8
            for (int i = 0; i < EMB; i++) s += We[k * EMB + i] * W1[(192 + i) * EMB + j];
            g_Md[idx] = s;
        }
    } else {
        if (threadIdx.x < EMB) {
            int j = threadIdx.x;
            float sAB = b1[j], sC = 0.f;
            #pragma unroll 8
            for (int i = 0; i < EMB; i++) {
                sAB += be[i] * W1[(64 + i) * EMB + j] + br[i] * W1[(128 + i) * EMB + j];
                sC  += be[i] * W1[(192 + i) * EMB + j];
            }
            g_biasAB[j] = sAB;
            g_biasC[j]  = sC;
        }
    }
}

// ---------------- node mma kernel: [128 x 64] @ [64 x 128] via tf32 mma ----------------
// smem floats: sNE[128*68]=8704 | sW[64*136]=8704
#define NODE_SME_BYTES ((8704 + 8704) * 4)

__global__ __launch_bounds__(256) void node_mma_kernel(const float* __restrict__ nodeEmb,
                                                       const int*   __restrict__ nodeBatch) {
    extern __shared__ float sm[];
    float* sNE = sm;           // 128 x 68 (tf32)
    float* sW  = sm + 8704;    // 64 x 136 = [Mb | Md] (tf32)

    int t = threadIdx.x;
    int n0 = blockIdx.x * 128;

    // fill node tile (zero-pad rows past NN)
    for (int i = t; i < 2048; i += 256) {
        int r = i >> 4, c4 = (i & 15) << 2;
        int n = n0 + r;
        float4 v = (n < NN) ? ((const float4*)nodeEmb)[(size_t)n * 16 + (i & 15)]
                            : make_float4(0.f, 0.f, 0.f, 0.f);
        float* d = &sNE[r * 68 + c4];
        d[0] = tf32r(v.x); d[1] = tf32r(v.y); d[2] = tf32r(v.z); d[3] = tf32r(v.w);
    }
    // fill [Mb | Md]
    for (int i = t; i < 1024; i += 256) {
        int r = i >> 4, c4 = (i & 15) << 2;
        float4 vb = ((const float4*)g_Mb)[i];
        float4 vd = ((const float4*)g_Md)[i];
        float* db = &sW[r * 136 + c4];
        float* dd = &sW[r * 136 + 64 + c4];
        db[0] = tf32r(vb.x); db[1] = tf32r(vb.y); db[2] = tf32r(vb.z); db[3] = tf32r(vb.w);
        dd[0] = tf32r(vd.x); dd[1] = tf32r(vd.y); dd[2] = tf32r(vd.z); dd[3] = tf32r(vd.w);
    }
    __syncthreads();

    int w = t >> 5, lane = t & 31;
    int g = lane >> 2, tig = lane & 3;
    int rA = w * 16 + g;

    float acc[64];
    #pragma unroll
    for (int j = 0; j < 64; j++) acc[j] = 0.f;

    #pragma unroll
    for (int kt = 0; kt < 8; kt++) {
        int k0 = kt * 8;
        uint32_t a0 = __float_as_uint(sNE[rA * 68 + k0 + tig]);
        uint32_t a1 = __float_as_uint(sNE[(rA + 8) * 68 + k0 + tig]);
        uint32_t a2 = __float_as_uint(sNE[rA * 68 + k0 + tig + 4]);
        uint32_t a3 = __float_as_uint(sNE[(rA + 8) * 68 + k0 + tig + 4]);
        #pragma unroll
        for (int nt = 0; nt < 16; nt++) {
            uint32_t b0 = __float_as_uint(sW[(k0 + tig) * 136 + nt * 8 + g]);
            uint32_t b1 = __float_as_uint(sW[(k0 + tig + 4) * 136 + nt * 8 + g]);
            mma_tf32(acc[nt*4], acc[nt*4+1], acc[nt*4+2], acc[nt*4+3],
                     a0, a1, a2, a3, b0, b1);
        }
    }

    // epilogue: add biases (+ Aq for ABn half), store to tables
    int nlo = n0 + rA, nhi = n0 + rA + 8;
    int qlo = (nlo < NN) ? nodeBatch[nlo] : 0;
    int qhi = (nhi < NN) ? nodeBatch[nhi] : 0;
    #pragma unroll
    for (int nt = 0; nt < 16; nt++) {
        int c = nt * 8 + 2 * tig;
        if (nt < 8) {  // ABn half
            float bA0 = g_biasAB[c], bA1 = g_biasAB[c + 1];
            if (nlo < NN) {
                g_ABn[(size_t)nlo * 64 + c]     = acc[nt*4+0] + bA0 + g_Aq[qlo * 64 + c];
                g_ABn[(size_t)nlo * 64 + c + 1] = acc[nt*4+1] + bA1 + g_Aq[qlo * 64 + c + 1];
            }
            if (nhi < NN) {
                g_ABn[(size_t)nhi * 64 + c]     = acc[nt*4+2] + bA0 + g_Aq[qhi * 64 + c];
                g_ABn[(size_t)nhi * 64 + c + 1] = acc[nt*4+3] + bA1 + g_Aq[qhi * 64 + c + 1];
            }
        } else {       // Cn half
            int cc = c - 64;
            float bC0 = g_biasC[cc], bC1 = g_biasC[cc + 1];
            if (nlo < NN) {
                g_Cn[(size_t)nlo * 64 + cc]     = acc[nt*4+0] + bC0;
                g_Cn[(size_t)nlo * 64 + cc + 1] = acc[nt*4+1] + bC1;
            }
            if (nhi < NN) {
                g_Cn[(size_t)nhi * 64 + cc]     = acc[nt*4+2] + bC0;
                g_Cn[(size_t)nhi * 64 + cc + 1] = acc[nt*4+3] + bC1;
            }
        }
    }
}

// ---------------- persistent edge kernel: tf32 mma, 128 edges/tile ----------------
// smem floats: sEE[128*68]=8704 | sM[64*72]=4608 | sW2[64*136]=8704 | sWh[128] | sb2[128] | sHT[256]
#define OFF_M  8704
#define OFF_W2 (8704 + 4608)
#define OFF_WH (8704 + 4608 + 8704)
#define OFF_B2 (OFF_WH + 128)
#define OFF_HT (OFF_B2 + 128)
#define SME_BYTES ((OFF_HT + 256) * 4)

__global__ __launch_bounds__(256, 2) void edge_kernel(const float* __restrict__ edgeEmb,
                                                      const int*   __restrict__ edgeIndex,
                                                      const float* __restrict__ W2,
                                                      const float* __restrict__ b2,
                                                      const float* __restrict__ Wh,
                                                      const float* __restrict__ bh,
                                                      float* __restrict__ out) {
    extern __shared__ float sm[];
    float* sEE = sm;                 // edge tile (tf32), later reused for H
    float* sM  = sm + OFF_M;
    float* sW2 = sm + OFF_W2;
    float* sWh = sm + OFF_WH;
    float* sb2 = sm + OFF_B2;
    int*   sHT = (int*)(sm + OFF_HT);

    int t = threadIdx.x;

    // ---- load weights ONCE ----
    for (int i = t; i < 1024; i += 256) {
        int r = i >> 4, c4 = (i & 15) << 2;
        float4 v = ((const float4*)g_M)[i];
        float* d = &sM[r * 72 + c4];
        d[0] = tf32r(v.x); d[1] = tf32r(v.y); d[2] = tf32r(v.z); d[3] = tf32r(v.w);
    }
    for (int i = t; i < 2048; i += 256) {
        int r = i >> 5, c4 = (i & 31) << 2;
        float4 v = ((const float4*)W2)[i];
        float* d = &sW2[r * 136 + c4];
        d[0] = tf32r(v.x); d[1] = tf32r(v.y); d[2] = tf32r(v.z); d[3] = tf32r(v.w);
    }
    if (t < 128) { sWh[t] = Wh[t]; sb2[t] = b2[t]; }
    float bhv = bh[0];

    int w = t >> 5, lane = t & 31;
    int g = lane >> 2, tig = lane & 3;
    int rA = w * 16 + g;

    // ---- prefetch first tile into registers ----
    float4 pv[8];
    int ih = 0, itl = 0;
    int tile = blockIdx.x;
    if (tile < NTILES) {
        int e0 = tile * 128;
        #pragma unroll
        for (int j = 0; j < 8; j++) {
            int i = t + 256 * j;
            pv[j] = ((const float4*)edgeEmb)[(size_t)(e0 + (i >> 4)) * 16 + (i & 15)];
        }
        if (t < 128) { ih = edgeIndex[e0 + t]; itl = edgeIndex[NE + e0 + t]; }
    }

    for (; tile < NTILES; tile += gridDim.x) {
        int e0 = tile * 128;
        __syncthreads();                 // prior tile's smem reads done
        #pragma unroll
        for (int j = 0; j < 8; j++) {
            int i = t + 256 * j;
            float* d = &sEE[(i >> 4) * 68 + ((i & 15) << 2)];
            d[0] = tf32r(pv[j].x); d[1] = tf32r(pv[j].y);
            d[2] = tf32r(pv[j].z); d[3] = tf32r(pv[j].w);
        }
        if (t < 128) { sHT[t] = ih; sHT[128 + t] = itl; }
        __syncthreads();                 // tile (and, first iter, weights) visible

        // ---- prefetch next tile (hidden under mma work) ----
        int nxt = tile + gridDim.x;
        if (nxt < NTILES) {
            int e0n = nxt * 128;
            #pragma unroll
            for (int j = 0; j < 8; j++) {
                int i = t + 256 * j;
                pv[j] = ((const float4*)edgeEmb)[(size_t)(e0n + (i >> 4)) * 16 + (i & 15)];
            }
            if (t < 128) { ih = edgeIndex[e0n + t]; itl = edgeIndex[NE + e0n + t]; }
        }

        // ---- gather G = ABn[head] + Cn[tail] directly into accumulators (L2) ----
        int h0 = sHT[rA],     t0 = sHT[128 + rA];
        int h1 = sHT[rA + 8], t1 = sHT[128 + rA + 8];
        const float2* A0 = (const float2*)(g_ABn + (size_t)h0 * EMB);
        const float2* C0 = (const float2*)(g_Cn  + (size_t)t0 * EMB);
        const float2* A1 = (const float2*)(g_ABn + (size_t)h1 * EMB);
        const float2* C1 = (const float2*)(g_Cn  + (size_t)t1 * EMB);

        float acc[32];
        #pragma unroll
        for (int nt = 0; nt < 8; nt++) {
            float2 a = A0[nt * 4 + tig], c = C0[nt * 4 + tig];
            float2 b = A1[nt * 4 + tig], d = C1[nt * 4 + tig];
            acc[nt*4+0] = a.x + c.x; acc[nt*4+1] = a.y + c.y;
            acc[nt*4+2] = b.x + d.x; acc[nt*4+3] = b.y + d.y;
        }

        // ---- stage 1: H = relu(EE @ M + G) ----
        #pragma unroll
        for (int kt = 0; kt < 8; kt++) {
            int k0 = kt * 8;
            uint32_t a0 = __float_as_uint(sEE[rA * 68 + k0 + tig]);
            uint32_t a1 = __float_as_uint(sEE[(rA + 8) * 68 + k0 + tig]);
            uint32_t a2 = __float_as_uint(sEE[rA * 68 + k0 + tig + 4]);
            uint32_t a3 = __float_as_uint(sEE[(rA + 8) * 68 + k0 + tig + 4]);
            #pragma unroll
            for (int nt = 0; nt < 8; nt++) {
                uint32_t b0 = __float_as_uint(sM[(k0 + tig) * 72 + nt * 8 + g]);
                uint32_t b1 = __float_as_uint(sM[(k0 + tig + 4) * 72 + nt * 8 + g]);
                mma_tf32(acc[nt*4], acc[nt*4+1], acc[nt*4+2], acc[nt*4+3],
                         a0, a1, a2, a3, b0, b1);
            }
        }
        __syncwarp();                    // all lanes done reading EE rows of this warp
        #pragma unroll
        for (int nt = 0; nt < 8; nt++) {
            int n0c = nt * 8 + 2 * tig;
            sEE[rA * 68 + n0c]           = fmaxf(acc[nt*4+0], 0.f);
            sEE[rA * 68 + n0c + 1]       = fmaxf(acc[nt*4+1], 0.f);
            sEE[(rA + 8) * 68 + n0c]     = fmaxf(acc[nt*4+2], 0.f);
            sEE[(rA + 8) * 68 + n0c + 1] = fmaxf(acc[nt*4+3], 0.f);
        }
        __syncwarp();                    // H visible to whole warp

        // ---- stage 2: z = relu(H @ W2 + b2); logit = z.Wh (two 8-nt halves) ----
        float p0 = 0.f, p1 = 0.f;
        #pragma unroll
        for (int half = 0; half < 2; half++) {
            int cbase = half * 64;
            float acc2[32];
            #pragma unroll
            for (int nt = 0; nt < 8; nt++) {
                float bz0 = sb2[cbase + nt * 8 + 2 * tig];
                float bz1 = sb2[cbase + nt * 8 + 2 * tig + 1];
                acc2[nt*4+0] = bz0; acc2[nt*4+1] = bz1;
                acc2[nt*4+2] = bz0; acc2[nt*4+3] = bz1;
            }
            #pragma unroll
            for (int kt = 0; kt < 8; kt++) {
                int k0 = kt * 8;
                uint32_t a0 = f2tf32(sEE[rA * 68 + k0 + tig]);
                uint32_t a1 = f2tf32(sEE[(rA + 8) * 68 + k0 + tig]);
                uint32_t a2 = f2tf32(sEE[rA * 68 + k0 + tig + 4]);
                uint32_t a3 = f2tf32(sEE[(rA + 8) * 68 + k0 + tig + 4]);
                #pragma unroll
                for (int nt = 0; nt < 8; nt++) {
                    uint32_t b0 = __float_as_uint(sW2[(k0 + tig) * 136 + cbase + nt * 8 + g]);
                    uint32_t b1 = __float_as_uint(sW2[(k0 + tig + 4) * 136 + cbase + nt * 8 + g]);
                    mma_tf32(acc2[nt*4], acc2[nt*4+1], acc2[nt*4+2], acc2[nt*4+3],
                             a0, a1, a2, a3, b0, b1);
                }
            }
            #pragma unroll
            for (int nt = 0; nt < 8; nt++) {
                float w0 = sWh[cbase + nt * 8 + 2 * tig];
                float w1 = sWh[cbase + nt * 8 + 2 * tig + 1];
                p0 += fmaxf(acc2[nt*4+0], 0.f) * w0 + fmaxf(acc2[nt*4+1], 0.f) * w1;
                p1 += fmaxf(acc2[nt*4+2], 0.f) * w0 + fmaxf(acc2[nt*4+3], 0.f) * w1;
            }
        }
        p0 += __shfl_xor_sync(0xffffffffu, p0, 1);
        p0 += __shfl_xor_sync(0xffffffffu, p0, 2);
        p1 += __shfl_xor_sync(0xffffffffu, p1, 1);
        p1 += __shfl_xor_sync(0xffffffffu, p1, 2);
        if (tig == 0) {
            out[e0 + rA]     = 1.f / (1.f + expf(-(p0 + bhv)));
            out[e0 + rA + 8] = 1.f / (1.f + expf(-(p1 + bhv)));
        }
    }
}

// ---------------- launch ----------------
extern "C" void kernel_launch(void* const* d_in, const int* in_sizes, int n_in,
                              void* d_out, int out_size) {
    const float* question_emb = (const float*)d_in[0];
    const float* node_emb     = (const float*)d_in[1];
    const float* edge_emb     = (const float*)d_in[2];
    const int*   edge_index   = (const int*)  d_in[3];
    const int*   node_batch   = (const int*)  d_in[4];
    const float* Wq = (const float*)d_in[5];
    const float* bq = (const float*)d_in[6];
    const float* We = (const float*)d_in[7];
    const float* be = (const float*)d_in[8];
    const float* Wr = (const float*)d_in[9];
    const float* br = (const float*)d_in[10];
    const float* W1 = (const float*)d_in[11];
    const float* b1 = (const float*)d_in[12];
    const float* W2 = (const float*)d_in[13];
    const float* b2 = (const float*)d_in[14];
    const float* Wh = (const float*)d_in[15];
    const float* bh = (const float*)d_in[16];
    float* out = (float*)d_out;

    prep0_kernel<<<16, 256>>>(question_emb, Wq, bq);
    prep1_kernel<<<65, 256>>>(We, be, Wr, br, W1, b1);

    cudaFuncSetAttribute(node_mma_kernel, cudaFuncAttributeMaxDynamicSharedMemorySize, NODE_SME_BYTES);
    node_mma_kernel<<<(NN + 127) / 128, 256, NODE_SME_BYTES>>>(node_emb, node_batch);

    cudaFuncSetAttribute(edge_kernel, cudaFuncAttributeMaxDynamicSharedMemorySize, SME_BYTES);
    edge_kernel<<<296, 256, SME_BYTES>>>(edge_emb, edge_index, W2, b2, Wh, bh, out);
}

// round 5
// speedup vs baseline: 19.9820x; 1.3371x over previous
#include <cuda_runtime.h>
#include <cuda_fp16.h>
#include <math.h>
#include <stdint.h>

#define EMB 64
#define HID 128
#define NN  50000
#define NE  800000
#define NQ  64
#define NTILES (NE / 128)

// ---------------- scratch (static device globals; no allocation) ----------------
__device__ float g_qr[NQ * EMB];        // q_repr = qe@Wq + bq
__device__ float g_Aq[NQ * EMB];        // q_repr @ W1a
__device__ float g_M [EMB * EMB];       // Wr @ W1c   (folded relation projection)
__device__ float g_Mb[EMB * EMB];       // We @ W1b
__device__ float g_Md[EMB * EMB];       // We @ W1d
__device__ float g_biasAB[EMB];         // b1 + be@W1b + br@W1c
__device__ float g_biasC [EMB];         // be@W1d
__device__ float g_ABn[NN * EMB];       // per-node: ne@Mb + biasAB + Aq[batch[n]]
__device__ float g_Cn [NN * EMB];       // per-node: ne@Md + biasC
__device__ __half2 g_Mt [EMB * 32];     // M transposed to [n][kpair], permuted fp16
__device__ __half2 g_W2t[HID * 32];     // W2 transposed to [n][kpair], permuted fp16

// ---------------- helpers ----------------
__device__ __forceinline__ uint32_t f2tf32(float x) {
    uint32_t r;
    asm("cvt.rna.tf32.f32 %0, %1;" : "=r"(r) : "f"(x));
    return r;
}
__device__ __forceinline__ float tf32r(float x) { return __uint_as_float(f2tf32(x)); }

__device__ __forceinline__ void mma_tf32(float& c0, float& c1, float& c2, float& c3,
                                         uint32_t a0, uint32_t a1, uint32_t a2, uint32_t a3,
                                         uint32_t b0, uint32_t b1) {
    asm volatile("mma.sync.aligned.m16n8k8.row.col.f32.tf32.tf32.f32 "
                 "{%0,%1,%2,%3}, {%4,%5,%6,%7}, {%8,%9}, {%0,%1,%2,%3};\n"
                 : "+f"(c0), "+f"(c1), "+f"(c2), "+f"(c3)
                 : "r"(a0), "r"(a1), "r"(a2), "r"(a3), "r"(b0), "r"(b1));
}
__device__ __forceinline__ void mma_f16(float& c0, float& c1, float& c2, float& c3,
                                        uint32_t a0, uint32_t a1, uint32_t a2, uint32_t a3,
                                        uint32_t b0, uint32_t b1) {
    asm volatile("mma.sync.aligned.m16n8k16.row.col.f32.f16.f16.f32 "
                 "{%0,%1,%2,%3}, {%4,%5,%6,%7}, {%8,%9}, {%0,%1,%2,%3};\n"
                 : "+f"(c0), "+f"(c1), "+f"(c2), "+f"(c3)
                 : "r"(a0), "r"(a1), "r"(a2), "r"(a3), "r"(b0), "r"(b1));
}
// permuted position of k-pair j: within each chunk of 8 pairs, order [0,4,1,5,2,6,3,7]
__device__ __forceinline__ int permp(int j) {
    int c = j >> 3, p = j & 7;
    return (c << 3) | ((p & 3) << 1) | (p >> 2);
}

// ---------------- prep 0: q_repr ----------------
__global__ void prep0_kernel(const float* __restrict__ qe,
                             const float* __restrict__ Wq,
                             const float* __restrict__ bq) {
    int idx = blockIdx.x * 256 + threadIdx.x;
    int q = idx >> 6, j = idx & 63;
    float s = bq[j];
    #pragma unroll 8
    for (int i = 0; i < EMB; i++) s += qe[q * EMB + i] * Wq[i * EMB + j];
    g_qr[idx] = s;
}

// ---------------- prep 1: folded matrices + biases ----------------
__global__ void prep1_kernel(const float* __restrict__ We,
                             const float* __restrict__ be,
                             const float* __restrict__ Wr,
                             const float* __restrict__ br,
                             const float* __restrict__ W1,
                             const float* __restrict__ b1) {
    int b = blockIdx.x;
    if (b < 64) {
        int m   = b >> 4;
        int idx = (b & 15) * 256 + threadIdx.x;
        int k = idx >> 6, j = idx & 63;
        float s = 0.f;
        if (m == 0) {
            #pragma unroll 8
            for (int i = 0; i < EMB; i++) s += g_qr[k * EMB + i] * W1[i * EMB + j];
            g_Aq[idx] = s;
        } else if (m == 1) {
            #pragma unroll 8
            for (int i = 0; i < EMB; i++) s += Wr[k * EMB + i] * W1[(128 + i) * EMB + j];
            g_M[idx] = s;
        } else if (m == 2) {
            #pragma unroll 8
            for (int i = 0; i < EMB; i++) s += We[k * EMB + i] * W1[(64 + i) * EMB + j];
            g_Mb[idx] = s;
        } else {
            #pragma unroll 8
            for (int i = 0; i < EMB; i++) s += We[k * EMB + i] * W1[(192 + i) * EMB + j];
            g_Md[idx] = s;
        }
    } else {
        if (threadIdx.x < EMB) {
            int j = threadIdx.x;
            float sAB = b1[j], sC = 0.f;
            #pragma unroll 8
            for (int i = 0; i < EMB; i++) {
                sAB += be[i] * W1[(64 + i) * EMB + j] + br[i] * W1[(128 + i) * EMB + j];
                sC  += be[i] * W1[(192 + i) * EMB + j];
            }
            g_biasAB[j] = sAB;
            g_biasC[j]  = sC;
        }
    }
}

// ---------------- prep 2: transpose+permute weights to fp16 B-fragment layout ----------------
__global__ void prep2_kernel(const float* __restrict__ W2) {
    int idx = blockIdx.x * 256 + threadIdx.x;   // 24 blocks -> 6144
    if (idx < 2048) {            // g_Mt: 64 n-rows x 32 kpairs
        int n = idx >> 5, pos = idx & 31;
        int c = pos >> 3, q = pos & 7;
        int p = (q >> 1) + ((q & 1) << 2);
        int k0 = (c << 4) + (p << 1);
        g_Mt[idx] = __floats2half2_rn(g_M[k0 * EMB + n], g_M[(k0 + 1) * EMB + n]);
    } else if (idx < 6144) {     // g_W2t: 128 n-rows x 32 kpairs
        int i2 = idx - 2048;
        int n = i2 >> 5, pos = i2 & 31;
        int c = pos >> 3, q = pos & 7;
        int p = (q >> 1) + ((q & 1) << 2);
        int k0 = (c << 4) + (p << 1);
        g_W2t[i2] = __floats2half2_rn(W2[k0 * HID + n], W2[(k0 + 1) * HID + n]);
    }
}

// ---------------- node mma kernel: [128 x 64] @ [64 x 128] via tf32 mma ----------------
#define NODE_SME_BYTES ((8704 + 8704) * 4)

__global__ __launch_bounds__(256) void node_mma_kernel(const float* __restrict__ nodeEmb,
                                                       const int*   __restrict__ nodeBatch) {
    extern __shared__ float sm[];
    float* sNE = sm;           // 128 x 68 (tf32)
    float* sW  = sm + 8704;    // 64 x 136 = [Mb | Md] (tf32)

    int t = threadIdx.x;
    int n0 = blockIdx.x * 128;

    for (int i = t; i < 2048; i += 256) {
        int r = i >> 4, c4 = (i & 15) << 2;
        int n = n0 + r;
        float4 v = (n < NN) ? ((const float4*)nodeEmb)[(size_t)n * 16 + (i & 15)]
                            : make_float4(0.f, 0.f, 0.f, 0.f);
        float* d = &sNE[r * 68 + c4];
        d[0] = tf32r(v.x); d[1] = tf32r(v.y); d[2] = tf32r(v.z); d[3] = tf32r(v.w);
    }
    for (int i = t; i < 1024; i += 256) {
        int r = i >> 4, c4 = (i & 15) << 2;
        float4 vb = ((const float4*)g_Mb)[i];
        float4 vd = ((const float4*)g_Md)[i];
        float* db = &sW[r * 136 + c4];
        float* dd = &sW[r * 136 + 64 + c4];
        db[0] = tf32r(vb.x); db[1] = tf32r(vb.y); db[2] = tf32r(vb.z); db[3] = tf32r(vb.w);
        dd[0] = tf32r(vd.x); dd[1] = tf32r(vd.y); dd[2] = tf32r(vd.z); dd[3] = tf32r(vd.w);
    }
    __syncthreads();

    int w = t >> 5, lane = t & 31;
    int g = lane >> 2, tig = lane & 3;
    int rA = w * 16 + g;

    float acc[64];
    #pragma unroll
    for (int j = 0; j < 64; j++) acc[j] = 0.f;

    #pragma unroll
    for (int kt = 0; kt < 8; kt++) {
        int k0 = kt * 8;
        uint32_t a0 = __float_as_uint(sNE[rA * 68 + k0 + tig]);
        uint32_t a1 = __float_as_uint(sNE[(rA + 8) * 68 + k0 + tig]);
        uint32_t a2 = __float_as_uint(sNE[rA * 68 + k0 + tig + 4]);
        uint32_t a3 = __float_as_uint(sNE[(rA + 8) * 68 + k0 + tig + 4]);
        #pragma unroll
        for (int nt = 0; nt < 16; nt++) {
            uint32_t b0 = __float_as_uint(sW[(k0 + tig) * 136 + nt * 8 + g]);
            uint32_t b1 = __float_as_uint(sW[(k0 + tig + 4) * 136 + nt * 8 + g]);
            mma_tf32(acc[nt*4], acc[nt*4+1], acc[nt*4+2], acc[nt*4+3],
                     a0, a1, a2, a3, b0, b1);
        }
    }

    int nlo = n0 + rA, nhi = n0 + rA + 8;
    int qlo = (nlo < NN) ? nodeBatch[nlo] : 0;
    int qhi = (nhi < NN) ? nodeBatch[nhi] : 0;
    #pragma unroll
    for (int nt = 0; nt < 16; nt++) {
        int c = nt * 8 + 2 * tig;
        if (nt < 8) {
            float bA0 = g_biasAB[c], bA1 = g_biasAB[c + 1];
            if (nlo < NN) {
                g_ABn[(size_t)nlo * 64 + c]     = acc[nt*4+0] + bA0 + g_Aq[qlo * 64 + c];
                g_ABn[(size_t)nlo * 64 + c + 1] = acc[nt*4+1] + bA1 + g_Aq[qlo * 64 + c + 1];
            }
            if (nhi < NN) {
                g_ABn[(size_t)nhi * 64 + c]     = acc[nt*4+2] + bA0 + g_Aq[qhi * 64 + c];
                g_ABn[(size_t)nhi * 64 + c + 1] = acc[nt*4+3] + bA1 + g_Aq[qhi * 64 + c + 1];
            }
        } else {
            int cc = c - 64;
            float bC0 = g_biasC[cc], bC1 = g_biasC[cc + 1];
            if (nlo < NN) {
                g_Cn[(size_t)nlo * 64 + cc]     = acc[nt*4+0] + bC0;
                g_Cn[(size_t)nlo * 64 + cc + 1] = acc[nt*4+1] + bC1;
            }
            if (nhi < NN) {
                g_Cn[(size_t)nhi * 64 + cc]     = acc[nt*4+2] + bC0;
                g_Cn[(size_t)nhi * 64 + cc + 1] = acc[nt*4+3] + bC1;
            }
        }
    }
}

// ---------------- persistent edge kernel: fp16 mma, 128 edges/tile ----------------
// smem (half2 units): sEE[128*40]=5120 | sMt[64*40]=2560 | sW2t[128*40]=5120
// then floats: sWh[128] | sb2[128] | int sHT[256]
#define H2_EE 0
#define H2_M  5120
#define H2_W2 7680
#define H2_END 12800
#define OFF_WH 0
#define OFF_B2 128
#define OFF_HT 256
#define SME_BYTES (H2_END * 4 + (256 + 256) * 4)

__global__ __launch_bounds__(256, 2) void edge_kernel(const float* __restrict__ edgeEmb,
                                                      const int*   __restrict__ edgeIndex,
                                                      const float* __restrict__ b2,
                                                      const float* __restrict__ Wh,
                                                      const float* __restrict__ bh,
                                                      float* __restrict__ out) {
    extern __shared__ __half2 smh[];
    __half2* sEE  = smh + H2_EE;     // 128 rows x stride 40 (32 kpairs + pad)
    __half2* sMt  = smh + H2_M;      // 64  rows x stride 40
    __half2* sW2t = smh + H2_W2;     // 128 rows x stride 40
    float*   fend = (float*)(smh + H2_END);
    float*   sWh  = fend + OFF_WH;
    float*   sb2  = fend + OFF_B2;
    int*     sHT  = (int*)(fend + OFF_HT);

    int t = threadIdx.x;

    // ---- load weights ONCE (already transposed/permuted fp16) ----
    for (int i = t; i < 2048; i += 256) sMt [(i >> 5) * 40 + (i & 31)] = g_Mt[i];
    for (int i = t; i < 4096; i += 256) sW2t[(i >> 5) * 40 + (i & 31)] = g_W2t[i];
    if (t < 128) { sWh[t] = Wh[t]; sb2[t] = b2[t]; }
    float bhv = bh[0];

    int w = t >> 5, lane = t & 31;
    int g = lane >> 2, tig = lane & 3;
    int rA = w * 16 + g;
    int tig2 = tig << 1;

    // precompute fill positions for this thread's 8 float4 chunks
    // chunk i (global): r = i>>4, q = i&15 -> pairs 2q, 2q+1 at permuted positions
    int fpos1[8], fpos2[8], frow[8];
    #pragma unroll
    for (int j = 0; j < 8; j++) {
        int i = t + 256 * j;
        frow[j]  = i >> 4;
        int q    = i & 15;
        fpos1[j] = permp(2 * q);
        fpos2[j] = permp(2 * q + 1);
    }

    // ---- prefetch first tile ----
    float4 pv[8];
    int ih = 0, itl = 0;
    int tile = blockIdx.x;
    if (tile < NTILES) {
        int e0 = tile * 128;
        #pragma unroll
        for (int j = 0; j < 8; j++) {
            int i = t + 256 * j;
            pv[j] = ((const float4*)edgeEmb)[(size_t)(e0 + (i >> 4)) * 16 + (i & 15)];
        }
        if (t < 128) { ih = edgeIndex[e0 + t]; itl = edgeIndex[NE + e0 + t]; }
    }

    for (; tile < NTILES; tile += gridDim.x) {
        int e0 = tile * 128;
        __syncthreads();                 // prior tile's smem reads done
        #pragma unroll
        for (int j = 0; j < 8; j++) {
            __half2* row = &sEE[frow[j] * 40];
            row[fpos1[j]] = __floats2half2_rn(pv[j].x, pv[j].y);
            row[fpos2[j]] = __floats2half2_rn(pv[j].z, pv[j].w);
        }
        if (t < 128) { sHT[t] = ih; sHT[128 + t] = itl; }
        __syncthreads();                 // tile (and, first iter, weights) visible

        // ---- prefetch next tile (hidden under mma work) ----
        int nxt = tile + gridDim.x;
        if (nxt < NTILES) {
            int e0n = nxt * 128;
            #pragma unroll
            for (int j = 0; j < 8; j++) {
                int i = t + 256 * j;
                pv[j] = ((const float4*)edgeEmb)[(size_t)(e0n + (i >> 4)) * 16 + (i & 15)];
            }
            if (t < 128) { ih = edgeIndex[e0n + t]; itl = edgeIndex[NE + e0n + t]; }
        }

        // ---- gather G = ABn[head] + Cn[tail] directly into accumulators (L2) ----
        int h0 = sHT[rA],     t0 = sHT[128 + rA];
        int h1 = sHT[rA + 8], t1 = sHT[128 + rA + 8];
        const float2* A0 = (const float2*)(g_ABn + (size_t)h0 * EMB);
        const float2* C0 = (const float2*)(g_Cn  + (size_t)t0 * EMB);
        const float2* A1 = (const float2*)(g_ABn + (size_t)h1 * EMB);
        const float2* C1 = (const float2*)(g_Cn  + (size_t)t1 * EMB);

        float acc[32];
        #pragma unroll
        for (int nt = 0; nt < 8; nt++) {
            float2 a = A0[nt * 4 + tig], c = C0[nt * 4 + tig];
            float2 b = A1[nt * 4 + tig], d = C1[nt * 4 + tig];
            acc[nt*4+0] = a.x + c.x; acc[nt*4+1] = a.y + c.y;
            acc[nt*4+2] = b.x + d.x; acc[nt*4+3] = b.y + d.y;
        }

        // ---- stage 1: H = relu(EE @ M + G), fp16 m16n8k16, 4 k-chunks ----
        const __half2* eeLo = &sEE[rA * 40 + tig2];
        const __half2* eeHi = &sEE[(rA + 8) * 40 + tig2];
        #pragma unroll
        for (int kt = 0; kt < 4; kt++) {
            int base = kt * 8;
            uint2 va = *(const uint2*)(eeLo + base);   // {a0, a2}
            uint2 vb = *(const uint2*)(eeHi + base);   // {a1, a3}
            #pragma unroll
            for (int nt = 0; nt < 8; nt++) {
                uint2 wb = *(const uint2*)(&sMt[(nt * 8 + g) * 40 + base + tig2]);
                mma_f16(acc[nt*4], acc[nt*4+1], acc[nt*4+2], acc[nt*4+3],
                        va.x, vb.x, va.y, vb.y, wb.x, wb.y);
            }
        }
        __syncwarp();                    // warp done reading its EE rows
        // pack H (cols 2tig,2tig+1 of each nt-chunk) as half2 into sEE at permuted pos
        #pragma unroll
        for (int nt = 0; nt < 8; nt++) {
            int pos = permp(nt * 4 + tig);
            sEE[rA * 40 + pos]       = __floats2half2_rn(fmaxf(acc[nt*4+0], 0.f),
                                                         fmaxf(acc[nt*4+1], 0.f));
            sEE[(rA + 8) * 40 + pos] = __floats2half2_rn(fmaxf(acc[nt*4+2], 0.f),
                                                         fmaxf(acc[nt*4+3], 0.f));
        }
        __syncwarp();                    // H visible to whole warp

        // ---- stage 2: z = relu(H @ W2 + b2); logit = z.Wh (two 64-col halves) ----
        float p0 = 0.f, p1 = 0.f;
        #pragma unroll
        for (int half = 0; half < 2; half++) {
            int cbase = half * 64;
            float acc2[32];
            #pragma unroll
            for (int nt = 0; nt < 8; nt++) {
                float bz0 = sb2[cbase + nt * 8 + tig2];
                float bz1 = sb2[cbase + nt * 8 + tig2 + 1];
                acc2[nt*4+0] = bz0; acc2[nt*4+1] = bz1;
                acc2[nt*4+2] = bz0; acc2[nt*4+3] = bz1;
            }
            #pragma unroll
            for (int kt = 0; kt < 4; kt++) {
                int base = kt * 8;
                uint2 va = *(const uint2*)(eeLo + base);
                uint2 vb = *(const uint2*)(eeHi + base);
                #pragma unroll
                for (int nt = 0; nt < 8; nt++) {
                    uint2 wb = *(const uint2*)(&sW2t[(cbase + nt * 8 + g) * 40 + base + tig2]);
                    mma_f16(acc2[nt*4], acc2[nt*4+1], acc2[nt*4+2], acc2[nt*4+3],
                            va.x, vb.x, va.y, vb.y, wb.x, wb.y);
                }
            }
            #pragma unroll
            for (int nt = 0; nt < 8; nt++) {
                float w0 = sWh[cbase + nt * 8 + tig2];
                float w1 = sWh[cbase + nt * 8 + tig2 + 1];
                p0 += fmaxf(acc2[nt*4+0], 0.f) * w0 + fmaxf(acc2[nt*4+1], 0.f) * w1;
                p1 += fmaxf(acc2[nt*4+2], 0.f) * w0 + fmaxf(acc2[nt*4+3], 0.f) * w1;
            }
        }
        p0 += __shfl_xor_sync(0xffffffffu, p0, 1);
        p0 += __shfl_xor_sync(0xffffffffu, p0, 2);
        p1 += __shfl_xor_sync(0xffffffffu, p1, 1);
        p1 += __shfl_xor_sync(0xffffffffu, p1, 2);
        if (tig == 0) {
            out[e0 + rA]     = 1.f / (1.f + expf(-(p0 + bhv)));
            out[e0 + rA + 8] = 1.f / (1.f + expf(-(p1 + bhv)));
        }
    }
}

// ---------------- launch ----------------
extern "C" void kernel_launch(void* const* d_in, const int* in_sizes, int n_in,
                              void* d_out, int out_size) {
    const float* question_emb = (const float*)d_in[0];
    const float* node_emb     = (const float*)d_in[1];
    const float* edge_emb     = (const float*)d_in[2];
    const int*   edge_index   = (const int*)  d_in[3];
    const int*   node_batch   = (const int*)  d_in[4];
    const float* Wq = (const float*)d_in[5];
    const float* bq = (const float*)d_in[6];
    const float* We = (const float*)d_in[7];
    const float* be = (const float*)d_in[8];
    const float* Wr = (const float*)d_in[9];
    const float* br = (const float*)d_in[10];
    const float* W1 = (const float*)d_in[11];
    const float* b1 = (const float*)d_in[12];
    const float* W2 = (const float*)d_in[13];
    const float* b2 = (const float*)d_in[14];
    const float* Wh = (const float*)d_in[15];
    const float* bh = (const float*)d_in[16];
    float* out = (float*)d_out;

    prep0_kernel<<<16, 256>>>(question_emb, Wq, bq);
    prep1_kernel<<<65, 256>>>(We, be, Wr, br, W1, b1);
    prep2_kernel<<<24, 256>>>(W2);

    cudaFuncSetAttribute(node_mma_kernel, cudaFuncAttributeMaxDynamicSharedMemorySize, NODE_SME_BYTES);
    node_mma_kernel<<<(NN + 127) / 128, 256, NODE_SME_BYTES>>>(node_emb, node_batch);

    cudaFuncSetAttribute(edge_kernel, cudaFuncAttributeMaxDynamicSharedMemorySize, SME_BYTES);
    edge_kernel<<<296, 256, SME_BYTES>>>(edge_emb, edge_index, b2, Wh, bh, out);
}